// round 11
// baseline (speedup 1.0000x reference)
#include <cuda_runtime.h>
#include <cuda_fp16.h>
#include <float.h>
#include <stdint.h>

// Morphological dilation2d (max-plus conv):
//   out[b,o,h,w] = max_{c,i,j}( x_pad[b,c,h+i,w+j] + wt[o,c,i,j] ),  zero padding participates.
// B=C=O=4, H=W=1024, k=5, pad=2.
//
// R11: R10 inner loop (dual column-group fp16x2, conflict-free 16B-lane LDS.128)
// + MLP-batched staging (10 LDG.64 in flight) + TH=32/256thr for 40 warps/SM
// and half the CTA-prologue count.

#define TH 32
#define TW 64
#define GP 4                 // outputs per group per thread
#define XROWS (TH + 4)       // 36
#define XCOLS 68             // half2 columns used (64 + halo 4)
#define XSTRIDE 72           // half2 stride: 288B, 16B-aligned
#define NQ (4 * XROWS * (XCOLS / 4))   // 2448 quads to stage

// duplicate low/high half of a packed half2 pair: returns raw b32
__device__ __forceinline__ unsigned dup_lo_u(unsigned p) {
    unsigned r; asm("prmt.b32 %0, %1, %1, 0x1010;" : "=r"(r) : "r"(p));
    return r;
}
__device__ __forceinline__ unsigned dup_hi_u(unsigned p) {
    unsigned r; asm("prmt.b32 %0, %1, %1, 0x3232;" : "=r"(r) : "r"(p));
    return r;
}

__global__ __launch_bounds__(256, 5)
void Morphology_84602265797171_kernel(const float* __restrict__ x,
                                      const float* __restrict__ wt,
                                      float* __restrict__ out) {
    __shared__ __align__(16) half2 xs[4][XROWS][XSTRIDE];   // dup pairs; 41.5 KB
    __shared__ __align__(16) uint4 wsm4[20][3];  // [ci]: 0=w01 j0-3, 1=w23 j0-3, 2={w01j4,w23j4,-,-}

    const int tid = threadIdx.x;
    const int b  = blockIdx.z;
    const int h0 = blockIdx.y * TH;
    const int w0 = blockIdx.x * TW;

    // --- prepack weights: wt layout [o][c][i][j]; tid -> (ci=tid/5, j=tid%5) ---
    if (tid < 100) {
        int ci = tid / 5;
        int j  = tid % 5;
        half2 w01 = __floats2half2_rn(wt[tid],       wt[tid + 100]);
        half2 w23 = __floats2half2_rn(wt[tid + 200], wt[tid + 300]);
        half2* base = (half2*)&wsm4[ci][0];
        if (j < 4) {
            base[j]     = w01;
            base[4 + j] = w23;
        } else {
            base[8] = w01;
            base[9] = w23;
        }
    }

    // --- stage x tile: 4 channels, 36 rows, 68 half2 cols (dup pairs) ---
    const float* xb = x + (size_t)b * 4 * 1024 * 1024;
    const bool interior = (h0 >= 2) && (h0 + TH + 2 <= 1024) &&
                          (w0 >= 2) && (w0 + XCOLS - 2 <= 1024);
    if (interior) {
        // MLP-batched: gather 5 iterations of 2x LDG.64 each (10 loads in flight),
        // then convert + STS.128.
        #pragma unroll 1
        for (int base0 = 0; base0 < NQ; base0 += 256 * 5) {
            float2 gv[5][2];
            int cc[5], rr[5], qq[5];
            bool pr[5];
            #pragma unroll
            for (int k = 0; k < 5; k++) {
                int idx = base0 + k * 256 + tid;
                pr[k] = (idx < NQ);
                int i2 = pr[k] ? idx : 0;
                cc[k] = i2 / (XROWS * (XCOLS / 4));
                int rem = i2 % (XROWS * (XCOLS / 4));
                rr[k] = rem / (XCOLS / 4);
                qq[k] = rem % (XCOLS / 4);
                const float* grow = xb + (size_t)cc[k] * 1024 * 1024
                                  + (size_t)(h0 - 2 + rr[k]) * 1024 + (w0 - 2) + qq[k] * 4;
                if (pr[k]) {
                    gv[k][0] = *(const float2*)grow;
                    gv[k][1] = *(const float2*)(grow + 2);
                }
            }
            #pragma unroll
            for (int k = 0; k < 5; k++) {
                if (pr[k]) {
                    half2 p0 = __floats2half2_rn(gv[k][0].x, gv[k][0].y);
                    half2 p1 = __floats2half2_rn(gv[k][1].x, gv[k][1].y);
                    unsigned u0 = *(unsigned*)&p0;
                    unsigned u1 = *(unsigned*)&p1;
                    uint4 v4 = make_uint4(dup_lo_u(u0), dup_hi_u(u0),
                                          dup_lo_u(u1), dup_hi_u(u1));
                    *(uint4*)&xs[cc[k]][rr[k]][qq[k] * 4] = v4;
                }
            }
        }
    } else {
        // border: predicated scalar loads
        #pragma unroll 1
        for (int g = tid; g < NQ; g += 256) {
            int c   = g / (XROWS * (XCOLS / 4));
            int rem = g % (XROWS * (XCOLS / 4));
            int r   = rem / (XCOLS / 4);
            int q   = rem % (XCOLS / 4);
            int gh  = h0 - 2 + r;
            const float* grow = xb + (size_t)c * 1024 * 1024 + (size_t)gh * 1024;
            float v[4];
            #pragma unroll
            for (int e = 0; e < 4; e++) {
                int gw = w0 - 2 + q * 4 + e;
                bool ok = ((unsigned)gh < 1024u) & ((unsigned)gw < 1024u);
                v[e] = ok ? grow[gw] : 0.0f;
            }
            half2* dst = &xs[c][r][q * 4];
            dst[0] = __half2half2(__float2half_rn(v[0]));
            dst[1] = __half2half2(__float2half_rn(v[1]));
            dst[2] = __half2half2(__float2half_rn(v[2]));
            dst[3] = __half2half2(__float2half_rn(v[3]));
        }
    }
    __syncthreads();

    const int th  = tid >> 3;            // 0..31   output row in tile
    const int tw0 = (tid & 7) * GP;      // 0..28   group0 first col (16B per lane)

    half2 a01[2][GP], a23[2][GP];        // [group][t]
    const half2 NEG = __half2half2(__float2half_rn(-60000.0f));
    #pragma unroll
    for (int ggg = 0; ggg < 2; ggg++)
        #pragma unroll
        for (int t = 0; t < GP; t++) { a01[ggg][t] = NEG; a23[ggg][t] = NEG; }

    #pragma unroll 1
    for (int c = 0; c < 4; c++) {
        #pragma unroll
        for (int i = 0; i < 5; i++) {
            const int ci = c * 5 + i;

            // weights: 3 uniform LDS.128 (broadcast)
            half2 w01[5], w23[5];
            {
                uint4 q0 = wsm4[ci][0];
                uint4 q1 = wsm4[ci][1];
                uint4 q2 = wsm4[ci][2];
                *(uint4*)&w01[0] = q0;
                *(uint4*)&w23[0] = q1;
                w01[4] = *(half2*)&q2.x;
                w23[4] = *(half2*)&q2.y;
            }
            const half2* rowp = &xs[c][th + i][0];

            #pragma unroll
            for (int grp = 0; grp < 2; grp++) {
                const int twg = tw0 + grp * 32;
                // 8 x pairs: 2x LDS.128, each quarter-warp contiguous 128B
                half2 xv[8];
                {
                    const uint4* xq = (const uint4*)(rowp + twg);
                    *(uint4*)&xv[0] = xq[0];
                    *(uint4*)&xv[4] = xq[1];
                }
                #pragma unroll
                for (int j = 0; j < 5; j++) {
                    #pragma unroll
                    for (int t = 0; t < GP; t++) {
                        half2 xp = xv[t + j];
                        a01[grp][t] = __hmax2(a01[grp][t], __hadd2(xp, w01[j]));
                        a23[grp][t] = __hmax2(a23[grp][t], __hadd2(xp, w23[j]));
                    }
                }
            }
        }
    }

    // --- epilogue: unpack, one float4 per (o, group) ---
    const size_t plane = (size_t)1024 * 1024;
    float* ob = out + (size_t)b * 4 * plane + (size_t)(h0 + th) * 1024 + w0;

    #pragma unroll
    for (int grp = 0; grp < 2; grp++) {
        const int twg = tw0 + grp * 32;
        float f0[GP], f1[GP], f2[GP], f3[GP];
        #pragma unroll
        for (int t = 0; t < GP; t++) {
            float2 p01 = __half22float2(a01[grp][t]);
            float2 p23 = __half22float2(a23[grp][t]);
            f0[t] = p01.x; f1[t] = p01.y; f2[t] = p23.x; f3[t] = p23.y;
        }
        *(float4*)(ob + 0 * plane + twg) = make_float4(f0[0], f0[1], f0[2], f0[3]);
        *(float4*)(ob + 1 * plane + twg) = make_float4(f1[0], f1[1], f1[2], f1[3]);
        *(float4*)(ob + 2 * plane + twg) = make_float4(f2[0], f2[1], f2[2], f2[3]);
        *(float4*)(ob + 3 * plane + twg) = make_float4(f3[0], f3[1], f3[2], f3[3]);
    }
}

extern "C" void kernel_launch(void* const* d_in, const int* in_sizes, int n_in,
                              void* d_out, int out_size) {
    const float* x  = (const float*)d_in[0];   // (4,4,1024,1024) f32
    const float* wt = (const float*)d_in[1];   // (4,4,5,5) f32
    float* out = (float*)d_out;                // (4,4,1024,1024) f32

    dim3 grid(1024 / TW, 1024 / TH, 4);        // (16, 32, 4)
    dim3 block(256);
    Morphology_84602265797171_kernel<<<grid, block>>>(x, wt, out);
}